// round 1
// baseline (speedup 1.0000x reference)
#include <cuda_runtime.h>
#include <cuda_bf16.h>
#include <cstdint>

#define NN 200000
#define CH 128
#define KK 27
#define DD 3
#define CC (CH*CH)                         // 16384
#define TILE_M 128
#define NTILES ((NN + TILE_M - 1) / TILE_M) // 1563
#define STAT_BLOCKS 512
#define WBLK (DD*KK)                        // 81 k-slices per weight tensor

// ---------------- device scratch (static: no allocs allowed) ----------------
__device__ __align__(16) __nv_bfloat16 g_xh[(size_t)(NN+1)*CH];
__device__ __align__(16) __nv_bfloat16 g_xl[(size_t)(NN+1)*CH];
__device__ __align__(16) __nv_bfloat16 g_hh[(size_t)(NN+1)*CH];
__device__ __align__(16) __nv_bfloat16 g_hl[(size_t)(NN+1)*CH];
__device__ __align__(16) float g_hbuf[(size_t)NN*CH];
__device__ __align__(16) float g_ybuf[(size_t)NN*CH];
__device__ __align__(16) __nv_bfloat16 g_wh[(size_t)2*WBLK*CC];
__device__ __align__(16) __nv_bfloat16 g_wl[(size_t)2*WBLK*CC];
__device__ float g_part_s[STAT_BLOCKS*CH];
__device__ float g_part_q[STAT_BLOCKS*CH];
__device__ float g_sum[CH];
__device__ float g_sq[CH];
__device__ float g_r[CH];

// ---------------- helpers ----------------
__device__ __forceinline__ void split2(float v, __nv_bfloat16& hi, __nv_bfloat16& lo) {
    hi = __float2bfloat16(v);
    lo = __float2bfloat16(v - __bfloat162float(hi));
}

__device__ __forceinline__ void mma16816(float* d, const uint32_t* a, const uint32_t* b) {
    asm volatile(
        "mma.sync.aligned.m16n8k16.row.col.f32.bf16.bf16.f32 "
        "{%0,%1,%2,%3},{%4,%5,%6,%7},{%8,%9},{%0,%1,%2,%3};"
        : "+f"(d[0]), "+f"(d[1]), "+f"(d[2]), "+f"(d[3])
        : "r"(a[0]), "r"(a[1]), "r"(a[2]), "r"(a[3]), "r"(b[0]), "r"(b[1]));
}

// ---------------- weight split + transpose: [ci][co] -> bf16 hi/lo [co][ci] ----------------
__global__ void split_w_kernel(const float* __restrict__ w1, const float* __restrict__ w2) {
    size_t i = (size_t)blockIdx.x*256 + threadIdx.x;
    if (i >= (size_t)2*WBLK*CC) return;
    size_t blk = i >> 14;               // which 128x128 slice (w1: 0..80, w2: 81..161)
    int j = (int)(i & (CC-1));
    int ci = j >> 7, co = j & 127;
    float v = (blk < WBLK) ? w1[blk*CC + j] : w2[(blk - (size_t)WBLK)*CC + j];
    size_t dst = blk*CC + (size_t)co*CH + ci;  // transposed within slice
    __nv_bfloat16 hi, lo; split2(v, hi, lo);
    g_wh[dst] = hi; g_wl[dst] = lo;
}

// ---------------- split x into hi/lo bf16 (row NN = zero sentinel) ----------------
__global__ void split_x_kernel(const float* __restrict__ x) {
    size_t i = (size_t)blockIdx.x*256 + threadIdx.x;
    if (i >= (size_t)(NN+1)*CH) return;
    float val = (i < (size_t)NN*CH) ? x[i] : 0.f;
    __nv_bfloat16 hi, lo; split2(val, hi, lo);
    g_xh[i] = hi; g_xl[i] = lo;
}

// ---------------- sparse conv: gather + 27x GEMM, bf16x3, mma.sync ----------------
__global__ void __launch_bounds__(256, 1)
conv_kernel(const __nv_bfloat16* __restrict__ Ah, const __nv_bfloat16* __restrict__ Al,
            const __nv_bfloat16* __restrict__ Wh, const __nv_bfloat16* __restrict__ Wl,
            const int* __restrict__ nbr, float* __restrict__ outp)
{
    extern __shared__ __nv_bfloat16 smem[];
    __nv_bfloat16* Ash = smem;                  // [128][136] padded
    __nv_bfloat16* Asl = smem + 128*136;
    __nv_bfloat16* Bsh = smem + 2*128*136;      // Wt[cout][cin], padded
    __nv_bfloat16* Bsl = smem + 3*128*136;
    int* sidx = (int*)(smem + 4*128*136);

    const int tid  = threadIdx.x;
    const int lane = tid & 31;
    const int warp = tid >> 5;
    const int wm = warp >> 2;       // 0..1  (64 rows each)
    const int wn = warp & 3;        // 0..3  (32 cols each)
    const int row0 = blockIdx.x * TILE_M;

    const int gr = lane >> 2;
    const int gc = (lane & 3) * 2;

    float acc[4][4][4];
    #pragma unroll
    for (int a = 0; a < 4; a++)
        #pragma unroll
        for (int b = 0; b < 4; b++)
            #pragma unroll
            for (int c = 0; c < 4; c++) acc[a][b][c] = 0.f;

    #pragma unroll 1
    for (int k = 0; k < KK; ++k) {
        __syncthreads();   // protect smem from previous iteration's readers
        if (tid < 128) {
            int r = row0 + tid;
            sidx[tid] = (r < NN) ? nbr[(size_t)k*NN + r] : NN;
        }
        __syncthreads();
        // gather A rows (hi/lo), 16B vectors
        #pragma unroll
        for (int p = 0; p < 8; ++p) {
            int i = tid + p*256;
            int r = i >> 4, cch = (i & 15) * 8;
            size_t src = (size_t)sidx[r]*CH + cch;
            *(uint4*)&Ash[r*136 + cch] = *(const uint4*)&Ah[src];
            *(uint4*)&Asl[r*136 + cch] = *(const uint4*)&Al[src];
        }
        // copy W_k (already transposed [cout][cin])
        const __nv_bfloat16* wkh = Wh + (size_t)k*CC;
        const __nv_bfloat16* wkl = Wl + (size_t)k*CC;
        #pragma unroll
        for (int p = 0; p < 8; ++p) {
            int i = tid + p*256;
            int r = i >> 4, cch = (i & 15) * 8;
            *(uint4*)&Bsh[r*136 + cch] = *(const uint4*)&wkh[r*CH + cch];
            *(uint4*)&Bsl[r*136 + cch] = *(const uint4*)&wkl[r*CH + cch];
        }
        __syncthreads();

        #pragma unroll 1
        for (int kc = 0; kc < 8; ++kc) {
            const int kb = kc*16;
            uint32_t ah[4][4], al[4][4], bh[4][2], bl[4][2];
            #pragma unroll
            for (int mi = 0; mi < 4; ++mi) {
                int rbase = wm*64 + mi*16 + gr;
                int o0 = rbase*136 + kb + gc;
                int o1 = (rbase+8)*136 + kb + gc;
                ah[mi][0] = *(const uint32_t*)&Ash[o0];
                ah[mi][1] = *(const uint32_t*)&Ash[o1];
                ah[mi][2] = *(const uint32_t*)&Ash[o0 + 8];
                ah[mi][3] = *(const uint32_t*)&Ash[o1 + 8];
                al[mi][0] = *(const uint32_t*)&Asl[o0];
                al[mi][1] = *(const uint32_t*)&Asl[o1];
                al[mi][2] = *(const uint32_t*)&Asl[o0 + 8];
                al[mi][3] = *(const uint32_t*)&Asl[o1 + 8];
            }
            #pragma unroll
            for (int ni = 0; ni < 4; ++ni) {
                int nrow = wn*32 + ni*8 + gr;
                int o = nrow*136 + kb + gc;
                bh[ni][0] = *(const uint32_t*)&Bsh[o];
                bh[ni][1] = *(const uint32_t*)&Bsh[o + 8];
                bl[ni][0] = *(const uint32_t*)&Bsl[o];
                bl[ni][1] = *(const uint32_t*)&Bsl[o + 8];
            }
            #pragma unroll
            for (int mi = 0; mi < 4; ++mi)
                #pragma unroll
                for (int ni = 0; ni < 4; ++ni) {
                    mma16816(acc[mi][ni], ah[mi], bh[ni]);   // hi*hi
                    mma16816(acc[mi][ni], ah[mi], bl[ni]);   // hi*lo
                    mma16816(acc[mi][ni], al[mi], bh[ni]);   // lo*hi
                }
        }
    }

    // store accumulators
    #pragma unroll
    for (int mi = 0; mi < 4; ++mi) {
        int r_ = row0 + wm*64 + mi*16 + gr;
        #pragma unroll
        for (int ni = 0; ni < 4; ++ni) {
            int col = wn*32 + ni*8 + gc;
            if (r_ < NN)
                *(float2*)&outp[(size_t)r_*CH + col] = make_float2(acc[mi][ni][0], acc[mi][ni][1]);
            if (r_ + 8 < NN)
                *(float2*)&outp[(size_t)(r_+8)*CH + col] = make_float2(acc[mi][ni][2], acc[mi][ni][3]);
        }
    }
}

// ---------------- BN stats: deterministic two-pass ----------------
__global__ void stats_kernel(const float* __restrict__ h) {
    int c = threadIdx.x;
    float s = 0.f, q = 0.f;
    for (int r = blockIdx.x; r < NN; r += STAT_BLOCKS) {
        float v = h[(size_t)r*CH + c];
        s += v; q += v*v;
    }
    g_part_s[blockIdx.x*CH + c] = s;
    g_part_q[blockIdx.x*CH + c] = q;
}

__global__ void reduce_kernel() {
    int c = threadIdx.x;
    float s = 0.f, q = 0.f;
    for (int b = 0; b < STAT_BLOCKS; ++b) {
        s += g_part_s[b*CH + c];
        q += g_part_q[b*CH + c];
    }
    g_sum[c] = s; g_sq[c] = q;
}

// ---------------- BN + ReLU + bf16 split (for conv2 input) ----------------
__global__ void bn_relu_split_kernel(const float* __restrict__ h,
                                     const float* __restrict__ g, const float* __restrict__ b) {
    size_t i = (size_t)blockIdx.x*256 + threadIdx.x;
    if (i >= (size_t)(NN+1)*CH) return;
    int c = (int)(i & (CH-1));
    float val = 0.f;
    if (i < (size_t)NN*CH) {
        float m = g_sum[c] * (1.f/NN);
        float v = g_sq[c] * (1.f/NN) - m*m;
        float sc = g[c] * rsqrtf(v + 1e-5f);
        val = fmaxf((h[i] - m)*sc + b[c], 0.f);
    }
    __nv_bfloat16 hi, lo; split2(val, hi, lo);
    g_hh[i] = hi; g_hl[i] = lo;
}

// ---------------- BN + accumulate into y ----------------
__global__ void bn_acc_kernel(const float* __restrict__ h,
                              const float* __restrict__ g, const float* __restrict__ b,
                              int first) {
    size_t i = (size_t)blockIdx.x*256 + threadIdx.x;
    if (i >= (size_t)NN*CH) return;
    int c = (int)(i & (CH-1));
    float m = g_sum[c] * (1.f/NN);
    float v = g_sq[c] * (1.f/NN) - m*m;
    float sc = g[c] * rsqrtf(v + 1e-5f);
    float bnv = (h[i] - m)*sc + b[c];
    g_ybuf[i] = first ? bnv : (g_ybuf[i] + bnv);
}

// ---------------- xout = relu(y + x), column sums for global pool ----------------
__global__ void relu_add_kernel(const float* __restrict__ x) {
    int c = threadIdx.x;
    float s = 0.f;
    for (int r = blockIdx.x; r < NN; r += STAT_BLOCKS) {
        size_t i = (size_t)r*CH + c;
        float v = fmaxf(g_ybuf[i] + x[i], 0.f);
        g_hbuf[i] = v;
        s += v;
    }
    g_part_s[blockIdx.x*CH + c] = s;
    g_part_q[blockIdx.x*CH + c] = 0.f;
}

// ---------------- r = xg @ Wb + blin ----------------
__global__ void make_r_kernel(const float* __restrict__ wlin, const float* __restrict__ blin) {
    int co = threadIdx.x;
    float acc = blin[co];
    for (int ci = 0; ci < CH; ++ci)
        acc += (g_sum[ci] * (1.f/NN)) * wlin[(size_t)(CH + ci)*CH + co];
    g_r[co] = acc;
}

// ---------------- out = xout @ Wa + r ----------------
__global__ void __launch_bounds__(256)
final_gemm_kernel(const float* __restrict__ wlin, float* __restrict__ outp) {
    __shared__ float Xs[64*33];
    __shared__ float Ws[32*132];
    int tid = threadIdx.x;
    int tr = tid >> 4, tc = tid & 15;
    int row0 = blockIdx.x * 64;
    float acc[4][8];
    #pragma unroll
    for (int i = 0; i < 4; ++i)
        #pragma unroll
        for (int j = 0; j < 8; ++j) acc[i][j] = 0.f;

    for (int cb = 0; cb < CH; cb += 32) {
        __syncthreads();
        #pragma unroll
        for (int p = 0; p < 8; ++p) {
            int i = tid + p*256;
            int r = i >> 5, cc = i & 31;
            Xs[r*33 + cc] = g_hbuf[(size_t)(row0 + r)*CH + cb + cc];
        }
        #pragma unroll
        for (int p = 0; p < 16; ++p) {
            int i = tid + p*256;
            int kk = i >> 7, co = i & 127;
            Ws[kk*132 + co] = wlin[(size_t)(cb + kk)*CH + co];
        }
        __syncthreads();
        #pragma unroll
        for (int kk = 0; kk < 32; ++kk) {
            float a[4];
            #pragma unroll
            for (int i = 0; i < 4; ++i) a[i] = Xs[(tr*4 + i)*33 + kk];
            float4 b0 = *(float4*)&Ws[kk*132 + tc*8];
            float4 b1 = *(float4*)&Ws[kk*132 + tc*8 + 4];
            float bb[8] = {b0.x,b0.y,b0.z,b0.w,b1.x,b1.y,b1.z,b1.w};
            #pragma unroll
            for (int i = 0; i < 4; ++i)
                #pragma unroll
                for (int j = 0; j < 8; ++j)
                    acc[i][j] += a[i]*bb[j];
        }
    }
    #pragma unroll
    for (int i = 0; i < 4; ++i) {
        int r = row0 + tr*4 + i;
        if (r >= NN) continue;
        #pragma unroll
        for (int j = 0; j < 8; ++j)
            outp[(size_t)r*CH + tc*8 + j] = acc[i][j] + g_r[tc*8 + j];
    }
}

// ---------------- launch ----------------
extern "C" void kernel_launch(void* const* d_in, const int* in_sizes, int n_in,
                              void* d_out, int out_size) {
    const float* x    = (const float*)d_in[0];
    const float* w1   = (const float*)d_in[1];
    const float* w2   = (const float*)d_in[2];
    const float* g1   = (const float*)d_in[3];
    const float* b1   = (const float*)d_in[4];
    const float* g2   = (const float*)d_in[5];
    const float* b2   = (const float*)d_in[6];
    const float* wlin = (const float*)d_in[7];
    const float* blin = (const float*)d_in[8];
    const int*   nbr  = (const int*)d_in[9];
    float* outp = (float*)d_out;

    const int SMEM_CONV = 4*128*136*2 + 128*(int)sizeof(int);   // 139264 + 512
    cudaFuncSetAttribute(conv_kernel, cudaFuncAttributeMaxDynamicSharedMemorySize, SMEM_CONV);

    __nv_bfloat16 *xh, *xl, *hh, *hl, *wh, *wl;
    float *h;
    cudaGetSymbolAddress((void**)&xh, g_xh);
    cudaGetSymbolAddress((void**)&xl, g_xl);
    cudaGetSymbolAddress((void**)&hh, g_hh);
    cudaGetSymbolAddress((void**)&hl, g_hl);
    cudaGetSymbolAddress((void**)&wh, g_wh);
    cudaGetSymbolAddress((void**)&wl, g_wl);
    cudaGetSymbolAddress((void**)&h,  g_hbuf);

    size_t nelem_split = (size_t)(NN+1)*CH;
    split_w_kernel<<<(int)((2ull*WBLK*CC + 255)/256), 256>>>(w1, w2);
    split_x_kernel<<<(int)((nelem_split + 255)/256), 256>>>(x);

    for (int d = 0; d < DD; ++d) {
        const int* nb = nbr + (size_t)d*KK*NN;
        conv_kernel<<<NTILES, 256, SMEM_CONV>>>(xh, xl,
            wh + (size_t)d*KK*CC, wl + (size_t)d*KK*CC, nb, h);
        stats_kernel<<<STAT_BLOCKS, CH>>>(h);
        reduce_kernel<<<1, CH>>>();
        bn_relu_split_kernel<<<(int)((nelem_split + 255)/256), 256>>>(h, g1 + d*CH, b1 + d*CH);
        conv_kernel<<<NTILES, 256, SMEM_CONV>>>(hh, hl,
            wh + (size_t)(WBLK + d*KK)*CC, wl + (size_t)(WBLK + d*KK)*CC, nb, h);
        stats_kernel<<<STAT_BLOCKS, CH>>>(h);
        reduce_kernel<<<1, CH>>>();
        bn_acc_kernel<<<(int)(((size_t)NN*CH + 255)/256), 256>>>(h, g2 + d*CH, b2 + d*CH, d == 0);
    }
    relu_add_kernel<<<STAT_BLOCKS, CH>>>(x);
    reduce_kernel<<<1, CH>>>();
    make_r_kernel<<<1, CH>>>(wlin, blin);
    final_gemm_kernel<<<NN/64 + 1, 256>>>(wlin, outp);
}